// round 8
// baseline (speedup 1.0000x reference)
#include <cuda_runtime.h>
#include <math.h>
#include <stdint.h>

#define NLEVELS   16
#define NENTRIES  524309u

struct Meta {
    float rinv[NLEVELS]; // RN_f32(1/es) — XLA constant-folded reciprocal
    int   en[NLEVELS];
    int   start_hash;
};

__device__ __forceinline__ float2 ldg_cg_f2(const float2* p) {
    float2 r;
    asm("ld.global.cg.v2.f32 {%0,%1}, [%2];" : "=f"(r.x), "=f"(r.y) : "l"(p));
    return r;
}

// Warp covers TWO points (2w, 2w+1), all 16 levels, 2 z-halves.
// Lane = (l, h); each thread processes both points -> 8 gathers in flight.
// Dense levels: lane pair (2k,2k+1) addresses differ by 8B -> one 128B line.
// Hashed levels: .cg (L2-only) so they don't evict dense tables from L1.
__global__ __launch_bounds__(256)
void hashgrid_fwd_kernel(const float* __restrict__ xyz,
                         const float2* __restrict__ data,
                         float2* __restrict__ out,
                         Meta meta, int npoints)
{
    int t  = blockIdx.x * blockDim.x + threadIdx.x;
    int w  = t >> 5;          // warp -> point pair
    int ll = t & 31;
    int l  = ll >> 1;         // level
    int h  = ll & 1;          // z-half

    int n0 = 2 * w;
    if (n0 >= npoints) return;
    bool has2 = (n0 + 1) < npoints;
    int n1 = has2 ? (n0 + 1) : n0;

    float rinv = meta.rinv[l];
    int   en   = meta.en[l];
    int   em   = en - 1;
    bool hashed = (l >= meta.start_hash);
    unsigned ue = (unsigned)en;
    const float2* __restrict__ tbl = data + (size_t)l * NENTRIES;

    // ---- per-point setup: compute indices + weights for both points ----
    unsigned idx[2][4];
    float    wgt[2][4];

#pragma unroll
    for (int p = 0; p < 2; p++) {
        int n = p ? n1 : n0;
        float px = __fadd_rn(__ldg(xyz + 3 * n + 0), 1.0f);
        float py = __fadd_rn(__ldg(xyz + 3 * n + 1), 1.0f);
        float pz = __fadd_rn(__ldg(xyz + 3 * n + 2), 1.0f);

        // XLA divide-by-constant: f = RN(p * RN(1/es))
        float fx = __fmul_rn(px, rinv);
        float fy = __fmul_rn(py, rinv);
        float fz = __fmul_rn(pz, rinv);

        // quirk-faithful corners: int32(f + off), fp32 add per corner
        int x0 = (int)fx;  int x1 = (int)__fadd_rn(fx, 1.0f);
        int y0 = (int)fy;  int y1 = (int)__fadd_rn(fy, 1.0f);
        int z0 = (int)fz;  int z1 = (int)__fadd_rn(fz, 1.0f);

        float ox = __fadd_rn(fx, -(float)x0);
        float oy = __fadd_rn(fy, -(float)y0);
        float oz = __fadd_rn(fz, -(float)z0);

        x0 = min(max(x0, 0), em);   x1 = min(max(x1, 0), em);
        y0 = min(max(y0, 0), em);   y1 = min(max(y1, 0), em);
        int zc = h ? z1 : z0;
        zc = min(max(zc, 0), em);

        uint64_t hxa[2] = { (uint64_t)(uint32_t)x0, (uint64_t)(uint32_t)x1 };
        uint64_t hya[2] = { (uint64_t)(uint32_t)y0 * 19349663ull,
                            (uint64_t)(uint32_t)y1 * 19349663ull };
        uint64_t hz     = (uint64_t)(uint32_t)zc * 83492791ull;

        unsigned dxa[2] = { (unsigned)x0 * ue * ue, (unsigned)x1 * ue * ue };
        unsigned dya[2] = { (unsigned)y0 * ue,      (unsigned)y1 * ue };

        float wxa[2] = { __saturatef(__fadd_rn(1.0f, -ox)), __saturatef(ox) };
        float wya[2] = { __saturatef(__fadd_rn(1.0f, -oy)), __saturatef(oy) };
        float wz     = h ? __saturatef(oz) : __saturatef(__fadd_rn(1.0f, -oz));

#pragma unroll
        for (int c = 0; c < 4; c++) {
            int bx = (c >> 1) & 1, by = c & 1;
            unsigned hidx = (unsigned)((hxa[bx] ^ hya[by] ^ hz) % (uint64_t)NENTRIES);
            unsigned didx = dxa[bx] + dya[by] + (unsigned)zc;
            idx[p][c] = hashed ? hidx : didx;
            wgt[p][c] = __fmul_rn(__fmul_rn(wxa[bx], wya[by]), wz);
        }
    }

    // ---- issue all 8 gathers (MLP=8); hashed -> .cg, dense -> .ca ----
    float2 v[2][4];
    if (hashed) {
#pragma unroll
        for (int p = 0; p < 2; p++)
#pragma unroll
            for (int c = 0; c < 4; c++) v[p][c] = ldg_cg_f2(&tbl[idx[p][c]]);
    } else {
#pragma unroll
        for (int p = 0; p < 2; p++)
#pragma unroll
            for (int c = 0; c < 4; c++) v[p][c] = __ldg(&tbl[idx[p][c]]);
    }

    // ---- weight-accumulate, combine z-halves, store ----
#pragma unroll
    for (int p = 0; p < 2; p++) {
        float accx = 0.0f, accy = 0.0f;
#pragma unroll
        for (int c = 0; c < 4; c++) {
            accx = __fadd_rn(accx, __fmul_rn(wgt[p][c], v[p][c].x));
            accy = __fadd_rn(accy, __fmul_rn(wgt[p][c], v[p][c].y));
        }
        accx = __fadd_rn(accx, __shfl_xor_sync(0xFFFFFFFFu, accx, 1));
        accy = __fadd_rn(accy, __shfl_xor_sync(0xFFFFFFFFu, accy, 1));
        if (h == 0 && (p == 0 || has2)) {
            int n = p ? n1 : n0;
            out[(size_t)n * NLEVELS + l] = make_float2(accx, accy);
        }
    }
}

extern "C" void kernel_launch(void* const* d_in, const int* in_sizes, int n_in,
                              void* d_out, int out_size)
{
    const float* xyz  = (const float*)d_in[0];
    const float* data = (const float*)d_in[1];
    int sx = in_sizes[0], sd = in_sizes[1];
    if (sx > sd) {
        const float* tmp = xyz; xyz = data; data = tmp;
        int ts = sx; sx = sd; sd = ts;
    }
    int npoints = sx / 3;

    // numpy _grid_meta() bit-exact via runtime libm pow (volatile blocks folding)
    static volatile double V_B = 1.38;
    static volatile double V_BASE = 16.0;
    static volatile double V_THIRD_NUM = 1.0;
    Meta m;
    m.start_hash = NLEVELS;
    double third = V_THIRD_NUM / 3.0;
    for (int i = 0; i < NLEVELS; i++) {
        double b   = V_B;
        double res = V_BASE * pow(b, (double)i);
        double vnd = pow(res, 3.0);
        long long vn = (long long)vnd;
        double vs  = pow(8.0 / (double)vn, third);
        long long en = (long long)(2.0 / vs);
        double esd = 2.0 / ((double)en - 1.0);
        float  esf = (float)esd;
        m.en[i]   = (int)en;
        m.rinv[i] = 1.0f / esf;
        if (m.start_hash == NLEVELS && vn > (long long)NENTRIES)
            m.start_hash = i;
    }

    int nwarps  = (npoints + 1) / 2;       // 1 warp per 2 points
    int total   = nwarps * 32;
    int threads = 256;
    int blocks  = (total + threads - 1) / threads;
    hashgrid_fwd_kernel<<<blocks, threads>>>(
        xyz, (const float2*)data, (float2*)d_out, m, npoints);
}